// round 7
// baseline (speedup 1.0000x reference)
#include <cuda_runtime.h>
#include <math.h>

#define TT 8192
#define NCL 8     // CTAs per direction (= cluster size) in the LSTM kernel

// ---------------- scratch (static device globals; no allocation) ----------
__device__ float g_xp[2][TT][1024];   // gate preactivations x@W_ih.T + b_ih + b_hh
__device__ float g_lstm[TT * 512];    // [T][512] = concat(hf, hb)
__device__ float g_logits[TT * 8];    // [T][8] padded (7 used)

__device__ __forceinline__ unsigned sm_addr(const void* p) {
    return (unsigned)__cvta_generic_to_shared(p);
}

// ---------------- x_proj GEMM: C[t][n] = emb[sent[t]] . W[n] + b1[n]+b2[n]
__global__ void __launch_bounds__(256) xproj_kernel(
    const int* __restrict__ sent, const float* __restrict__ emb,
    const float* __restrict__ Wf, const float* __restrict__ b1f, const float* __restrict__ b2f,
    const float* __restrict__ Wb, const float* __restrict__ b1b, const float* __restrict__ b2b)
{
    int dir = blockIdx.z;
    const float* W  = dir ? Wb  : Wf;
    const float* b1 = dir ? b1b : b1f;
    const float* b2 = dir ? b2b : b2f;
    int t0 = blockIdx.x * 64;
    int n0 = blockIdx.y * 64;

    __shared__ __align__(16) float As[16][68];
    __shared__ __align__(16) float Bs[16][68];
    __shared__ int sent_s[64];

    int tid = threadIdx.x;
    if (tid < 64) sent_s[tid] = sent[t0 + tid];
    __syncthreads();

    int tx = tid & 15;
    int ty = tid >> 4;
    float acc[4][4];
#pragma unroll
    for (int i = 0; i < 4; i++)
#pragma unroll
        for (int j = 0; j < 4; j++) acc[i][j] = 0.f;

    int kk = tid & 15;
    int m0 = tid >> 4;
    for (int k0 = 0; k0 < 256; k0 += 16) {
#pragma unroll
        for (int r = 0; r < 4; r++) {
            int mm = m0 + 16 * r;
            As[kk][mm] = emb[(long long)sent_s[mm] * 256 + k0 + kk];
            Bs[kk][mm] = W[(long long)(n0 + mm) * 256 + k0 + kk];
        }
        __syncthreads();
#pragma unroll
        for (int k2 = 0; k2 < 16; k2++) {
            float4 fa = *(const float4*)&As[k2][ty * 4];
            float4 fb = *(const float4*)&Bs[k2][tx * 4];
            float a[4] = {fa.x, fa.y, fa.z, fa.w};
            float b[4] = {fb.x, fb.y, fb.z, fb.w};
#pragma unroll
            for (int i = 0; i < 4; i++)
#pragma unroll
                for (int j = 0; j < 4; j++)
                    acc[i][j] = fmaf(a[i], b[j], acc[i][j]);
        }
        __syncthreads();
    }
#pragma unroll
    for (int i = 0; i < 4; i++) {
        int t = t0 + ty * 4 + i;
#pragma unroll
        for (int j = 0; j < 4; j++) {
            int n = n0 + tx * 4 + j;
            g_xp[dir][t][n] = acc[i][j] + b1[n] + b2[n];
        }
    }
}

// ---------------- BiLSTM recurrence: overlapped DSMEM pipeline -----------
// 16 CTAs, cluster (8,1,1). CTA rank owns h units rank*32..+31 (128 rows).
// Thread layout as R6: lr = tid>>1 (row 0..127), halfsel = tid&1 (which
// 128-column half). h_buf is per-producer [parity][8][36] (36-stride: 16B
// aligned + bank shift). The half-dot consumes its 4 producer slices in
// order, each gated by an acquire-spin on that producer's flag. After the
// gate reduction + ONE syncthreads, warp 0 alone does activations, stores
// h_stage, pushes the CTA slice to all 8 CTAs and releases the flag; warps
// 1..7 run ahead into the next step's spins. gate_s parity double-buffered.
__global__ void __cluster_dims__(NCL, 1, 1) __launch_bounds__(256, 1) lstm_kernel(
    const float* __restrict__ Whhf, const float* __restrict__ Whhb,
    const float* __restrict__ h0, const float* __restrict__ c0)
{
    __shared__ __align__(16) float h_buf[2][8][36];
    __shared__ __align__(16) float h_stage[32];
    __shared__ float gate_s[2][128];
    __shared__ __align__(16) unsigned flags[8];

    unsigned rank;
    asm("mov.u32 %0, %%cluster_ctarank;" : "=r"(rank));
    int dir = blockIdx.x >> 3;
    int tid = threadIdx.x;
    int lane = tid & 31;
    int lr = tid >> 1;            // local row 0..127  (= gate*32 + jl)
    int halfsel = tid & 1;        // which 128-half of the 256-dot
    int gate = lr >> 5;
    int jl = lr & 31;
    int jglob = (int)rank * 32 + jl;
    int rowg = gate * 256 + jglob;
    const float* Whh = dir ? Whhb : Whhf;

    // 32 float4 weights in registers (cols halfsel*128 .. +127 of row rowg)
    float4 w[32];
    const float4* wsrc = (const float4*)(Whh + (long long)rowg * 256 + halfsel * 128);
#pragma unroll
    for (int i = 0; i < 32; i++) w[i] = wsrc[i];

    // init h(0) slices (local copy of full h0), flags, c
    if (tid < 256) h_buf[0][tid >> 5][tid & 31] = h0[dir * 256 + tid];
    if (tid < 8) flags[tid] = 0u;
    float cst = (tid < 32) ? c0[dir * 256 + (int)rank * 32 + tid] : 0.f;
    __syncthreads();
    asm volatile("barrier.cluster.arrive.aligned;" ::: "memory");
    asm volatile("barrier.cluster.wait.aligned;" ::: "memory");

    unsigned flags_sa = sm_addr(flags);
    unsigned hbuf_sa  = sm_addr(h_buf);

    // pusher lanes (warp 0, lane<8): peer CTA = lane; two parity dests
    unsigned dsth0 = 0, dsth1 = 0, dstfl = 0;
    if (tid < 8) {
        unsigned l0 = hbuf_sa + (unsigned)((0 * 8 + (int)rank) * 36) * 4u;
        unsigned l1 = hbuf_sa + (unsigned)((1 * 8 + (int)rank) * 36) * 4u;
        unsigned lf = flags_sa + 4u * rank;
        asm("mapa.shared::cluster.u32 %0, %1, %2;" : "=r"(dsth0) : "r"(l0), "r"((unsigned)tid));
        asm("mapa.shared::cluster.u32 %0, %1, %2;" : "=r"(dsth1) : "r"(l1), "r"((unsigned)tid));
        asm("mapa.shared::cluster.u32 %0, %1, %2;" : "=r"(dstfl) : "r"(lf), "r"((unsigned)tid));
    }

    const float* xbase = &g_xp[dir][0][0];
    float xv = 0.f;
    if (halfsel == 0) xv = __ldcg(xbase + (long long)(dir ? TT - 1 : 0) * 1024 + rowg);

    int halfbase = halfsel * 4;
    bool iswarp0 = (tid < 32);

    for (int s = 1; s <= TT; s++) {
        int t = dir ? (TT - s) : (s - 1);
        int par = (s - 1) & 1;
        unsigned need = (unsigned)(s - 1);

        // ---- per-slice acquire-gated half-dot ----
        float a0 = 0.f, a1 = 0.f, a2 = 0.f, a3 = 0.f;
#pragma unroll
        for (int pp = 0; pp < 4; pp++) {
            int p = halfbase + pp;
            unsigned fvv;
            do {
                asm volatile("ld.acquire.cluster.shared::cta.u32 %0, [%1];"
                             : "=r"(fvv) : "r"(flags_sa + 4u * (unsigned)p) : "memory");
            } while (fvv < need);
            const float4* sp = (const float4*)&h_buf[par][p][0];
            float4 hA = sp[0]; float4 wA = w[pp * 8 + 0];
            a0 = fmaf(wA.x, hA.x, a0); a0 = fmaf(wA.y, hA.y, a0);
            a0 = fmaf(wA.z, hA.z, a0); a0 = fmaf(wA.w, hA.w, a0);
            float4 hB = sp[1]; float4 wB = w[pp * 8 + 1];
            a1 = fmaf(wB.x, hB.x, a1); a1 = fmaf(wB.y, hB.y, a1);
            a1 = fmaf(wB.z, hB.z, a1); a1 = fmaf(wB.w, hB.w, a1);
            float4 hC = sp[2]; float4 wC = w[pp * 8 + 2];
            a2 = fmaf(wC.x, hC.x, a2); a2 = fmaf(wC.y, hC.y, a2);
            a2 = fmaf(wC.z, hC.z, a2); a2 = fmaf(wC.w, hC.w, a2);
            float4 hD = sp[3]; float4 wD = w[pp * 8 + 3];
            a3 = fmaf(wD.x, hD.x, a3); a3 = fmaf(wD.y, hD.y, a3);
            a3 = fmaf(wD.z, hD.z, a3); a3 = fmaf(wD.w, hD.w, a3);
            float4 hE = sp[4]; float4 wE = w[pp * 8 + 4];
            a0 = fmaf(wE.x, hE.x, a0); a0 = fmaf(wE.y, hE.y, a0);
            a0 = fmaf(wE.z, hE.z, a0); a0 = fmaf(wE.w, hE.w, a0);
            float4 hF = sp[5]; float4 wF = w[pp * 8 + 5];
            a1 = fmaf(wF.x, hF.x, a1); a1 = fmaf(wF.y, hF.y, a1);
            a1 = fmaf(wF.z, hF.z, a1); a1 = fmaf(wF.w, hF.w, a1);
            float4 hG = sp[6]; float4 wG = w[pp * 8 + 6];
            a2 = fmaf(wG.x, hG.x, a2); a2 = fmaf(wG.y, hG.y, a2);
            a2 = fmaf(wG.z, hG.z, a2); a2 = fmaf(wG.w, hG.w, a2);
            float4 hH = sp[7]; float4 wH = w[pp * 8 + 7];
            a3 = fmaf(wH.x, hH.x, a3); a3 = fmaf(wH.y, hH.y, a3);
            a3 = fmaf(wH.z, hH.z, a3); a3 = fmaf(wH.w, hH.w, a3);
        }
        float sum = (a0 + a1) + (a2 + a3);
        sum += __shfl_xor_sync(0xffffffffu, sum, 1);   // combine the two halves

        // prefetch next step's x while the tail of this step runs
        float xvn = 0.f;
        if (halfsel == 0 && s < TT)
            xvn = __ldcg(xbase + (long long)(dir ? TT - 1 - s : s) * 1024 + rowg);
        if (halfsel == 0) gate_s[s & 1][lr] = sum + xv;
        xv = xvn;
        __syncthreads();   // sync#1: gate_s[s&1] complete; orders all h_buf reads

        // ---- warp 0 only: activations, state, push, release ----
        if (iswarp0) {
            float gi = gate_s[s & 1][lane];
            float gf = gate_s[s & 1][32 + lane];
            float gg = gate_s[s & 1][64 + lane];
            float go = gate_s[s & 1][96 + lane];
            gi = __fdividef(1.f, 1.f + __expf(-gi));
            gf = __fdividef(1.f, 1.f + __expf(-gf));
            go = __fdividef(1.f, 1.f + __expf(-go));
            gg = __fdividef(2.f, 1.f + __expf(-2.f * gg)) - 1.f;   // tanh
            cst = gf * cst + gi * gg;
            float hv = go * (__fdividef(2.f, 1.f + __expf(-2.f * cst)) - 1.f);
            h_stage[lane] = hv;
            __stcg(&g_lstm[(long long)t * 512 + dir * 256 + (int)rank * 32 + lane], hv);
            __syncwarp();
            if (lane < 8) {
                unsigned dh = (s & 1) ? dsth1 : dsth0;
                const float4* st4 = (const float4*)h_stage;
#pragma unroll
                for (int i = 0; i < 8; i++) {
                    float4 v = st4[i];
                    asm volatile("st.shared::cluster.v4.f32 [%0], {%1,%2,%3,%4};"
                                 :: "r"(dh + 16u * i),
                                    "f"(v.x), "f"(v.y), "f"(v.z), "f"(v.w) : "memory");
                }
                asm volatile("st.release.cluster.shared::cluster.u32 [%0], %1;"
                             :: "r"(dstfl), "r"((unsigned)s) : "memory");
            }
        }
        // warps 1..7 fall through into the next step's acquire-spins
    }
}

// ---------------- logits = lstm_out @ W_out.T + b_out --------------------
__global__ void __launch_bounds__(256) logits_kernel(
    const float* __restrict__ Wout, const float* __restrict__ bout)
{
    __shared__ float Ws[7 * 512];
    int tid = threadIdx.x;
    for (int i = tid; i < 7 * 512; i += 256) Ws[i] = Wout[i];
    __syncthreads();

    int t = blockIdx.x * 8 + (tid >> 5);
    int lane = tid & 31;
    float acc[7];
#pragma unroll
    for (int j = 0; j < 7; j++) acc[j] = 0.f;
#pragma unroll
    for (int i = 0; i < 16; i++) {
        int k = lane + 32 * i;
        float v = g_lstm[(long long)t * 512 + k];
#pragma unroll
        for (int j = 0; j < 7; j++)
            acc[j] = fmaf(v, Ws[j * 512 + k], acc[j]);
    }
#pragma unroll
    for (int j = 0; j < 7; j++)
#pragma unroll
        for (int o = 16; o > 0; o >>= 1)
            acc[j] += __shfl_xor_sync(0xffffffffu, acc[j], o);
    if (lane < 7) g_logits[t * 8 + lane] = acc[lane] + bout[lane];
    else if (lane == 7) g_logits[t * 8 + 7] = 0.f;
}

// ---------------- Viterbi: replicated-fv single warp ---------------------
__global__ void viterbi_kernel(const float* __restrict__ trans,
                               float* __restrict__ out, int out_size)
{
    __shared__ unsigned bp_s[TT];
    __shared__ __align__(16) float feat_s[2][32][8];

    int lane = threadIdx.x;
    int n = (lane < 7) ? lane : 0;           // each lane owns target tag n
    float tn[7], tsp[7], f[7];
#pragma unroll
    for (int p = 0; p < 7; p++) tn[p] = trans[n * 7 + p];
#pragma unroll
    for (int p = 0; p < 7; p++) tsp[p] = trans[6 * 7 + p];   // STOP row
#pragma unroll
    for (int p = 0; p < 7; p++) f[p] = (p == 5) ? 0.f : -10000.f;  // START=5

    float4 p0 = *(const float4*)&g_logits[lane * 8];
    float4 p1 = *(const float4*)&g_logits[lane * 8 + 4];
    *(float4*)&feat_s[0][lane][0] = p0;
    *(float4*)&feat_s[0][lane][4] = p1;
    __syncwarp();

    for (int tile = 0; tile < TT / 32; tile++) {
        int buf = tile & 1;
        if (tile < TT / 32 - 1) {
            const float* src = &g_logits[((tile + 1) * 32 + lane) * 8];
            p0 = *(const float4*)src;
            p1 = *(const float4*)(src + 4);
        }
#pragma unroll 4
        for (int s2 = 0; s2 < 32; s2++) {
            int t = tile * 32 + s2;
            float c[7];
#pragma unroll
            for (int p = 0; p < 7; p++) c[p] = f[p] + tn[p];
            float m01 = fmaxf(c[0], c[1]), m23 = fmaxf(c[2], c[3]);
            float m45 = fmaxf(c[4], c[5]);
            float m = fmaxf(fmaxf(m01, m23), fmaxf(m45, c[6]));
            // first-index argmax (exact equality; m is bitwise one of c[p])
            int bi = 6;
            bi = (c[5] == m) ? 5 : bi;
            bi = (c[4] == m) ? 4 : bi;
            bi = (c[3] == m) ? 3 : bi;
            bi = (c[2] == m) ? 2 : bi;
            bi = (c[1] == m) ? 1 : bi;
            bi = (c[0] == m) ? 0 : bi;
            float fnew = m + feat_s[buf][s2][n];
#pragma unroll
            for (int p = 0; p < 7; p++) f[p] = __shfl_sync(0xffffffffu, fnew, p);
            unsigned contrib = (lane < 7) ? ((unsigned)bi << (3 * lane)) : 0u;
            unsigned word = __reduce_or_sync(0xffffffffu, contrib);
            if (lane == 0) bp_s[t] = word;
        }
        __syncwarp();
        if (tile < TT / 32 - 1) {
            *(float4*)&feat_s[buf ^ 1][lane][0] = p0;
            *(float4*)&feat_s[buf ^ 1][lane][4] = p1;
        }
        __syncwarp();
    }

    // termination (replicated in every lane)
    float tm[7];
#pragma unroll
    for (int p = 0; p < 7; p++) tm[p] = f[p] + tsp[p];
    float m01 = fmaxf(tm[0], tm[1]), m23 = fmaxf(tm[2], tm[3]);
    float m45 = fmaxf(tm[4], tm[5]);
    float bestv = fmaxf(fmaxf(m01, m23), fmaxf(m45, tm[6]));
    int bestn = 6;
    bestn = (tm[5] == bestv) ? 5 : bestn;
    bestn = (tm[4] == bestv) ? 4 : bestn;
    bestn = (tm[3] == bestv) ? 3 : bestn;
    bestn = (tm[2] == bestv) ? 2 : bestn;
    bestn = (tm[1] == bestv) ? 1 : bestn;
    bestn = (tm[0] == bestv) ? 0 : bestn;

    for (int i = 1 + TT + lane; i < out_size; i += 32) out[i] = 0.f;
    if (lane == 0) {
        out[0] = bestv;
        int tag = bestn;
        for (int t = TT - 1; t >= 0; t--) {
            out[1 + t] = (float)tag;
            tag = (int)((bp_s[t] >> (3 * tag)) & 7u);
        }
    }
}

// ---------------- launch ---------------------------------------------------
extern "C" void kernel_launch(void* const* d_in, const int* in_sizes, int n_in,
                              void* d_out, int out_size)
{
    const int*   sent  = (const int*)d_in[0];
    const float* emb   = (const float*)d_in[1];
    const float* Wihf  = (const float*)d_in[2];
    const float* Whhf  = (const float*)d_in[3];
    const float* bihf  = (const float*)d_in[4];
    const float* bhhf  = (const float*)d_in[5];
    const float* Wihb  = (const float*)d_in[6];
    const float* Whhb  = (const float*)d_in[7];
    const float* bihb  = (const float*)d_in[8];
    const float* bhhb  = (const float*)d_in[9];
    const float* h0    = (const float*)d_in[10];
    const float* c0    = (const float*)d_in[11];
    const float* Wout  = (const float*)d_in[12];
    const float* bout  = (const float*)d_in[13];
    const float* trans = (const float*)d_in[14];
    float* out = (float*)d_out;

    xproj_kernel<<<dim3(TT / 64, 1024 / 64, 2), 256>>>(
        sent, emb, Wihf, bihf, bhhf, Wihb, bihb, bhhb);
    lstm_kernel<<<2 * NCL, 256>>>(Whhf, Whhb, h0, c0);
    logits_kernel<<<TT / 8, 256>>>(Wout, bout);
    viterbi_kernel<<<1, 32>>>(trans, out, out_size);
}

// round 8
// speedup vs baseline: 1.0725x; 1.0725x over previous
#include <cuda_runtime.h>
#include <math.h>

#define TT 8192
#define NCL 16    // CTAs per direction (= cluster size) in the LSTM kernel

// ---------------- scratch (static device globals; no allocation) ----------
__device__ float g_xp[2][TT][1024];   // gate preactivations x@W_ih.T + b_ih + b_hh
__device__ float g_lstm[TT * 512];    // [T][512] = concat(hf, hb)
__device__ float g_logits[TT * 8];    // [T][8] padded (7 used)

__device__ __forceinline__ unsigned sm_addr(const void* p) {
    return (unsigned)__cvta_generic_to_shared(p);
}

// ---------------- x_proj GEMM: C[t][n] = emb[sent[t]] . W[n] + b1[n]+b2[n]
__global__ void __launch_bounds__(256) xproj_kernel(
    const int* __restrict__ sent, const float* __restrict__ emb,
    const float* __restrict__ Wf, const float* __restrict__ b1f, const float* __restrict__ b2f,
    const float* __restrict__ Wb, const float* __restrict__ b1b, const float* __restrict__ b2b)
{
    int dir = blockIdx.z;
    const float* W  = dir ? Wb  : Wf;
    const float* b1 = dir ? b1b : b1f;
    const float* b2 = dir ? b2b : b2f;
    int t0 = blockIdx.x * 64;
    int n0 = blockIdx.y * 64;

    __shared__ __align__(16) float As[16][68];
    __shared__ __align__(16) float Bs[16][68];
    __shared__ int sent_s[64];

    int tid = threadIdx.x;
    if (tid < 64) sent_s[tid] = sent[t0 + tid];
    __syncthreads();

    int tx = tid & 15;
    int ty = tid >> 4;
    float acc[4][4];
#pragma unroll
    for (int i = 0; i < 4; i++)
#pragma unroll
        for (int j = 0; j < 4; j++) acc[i][j] = 0.f;

    int kk = tid & 15;
    int m0 = tid >> 4;
    for (int k0 = 0; k0 < 256; k0 += 16) {
#pragma unroll
        for (int r = 0; r < 4; r++) {
            int mm = m0 + 16 * r;
            As[kk][mm] = emb[(long long)sent_s[mm] * 256 + k0 + kk];
            Bs[kk][mm] = W[(long long)(n0 + mm) * 256 + k0 + kk];
        }
        __syncthreads();
#pragma unroll
        for (int k2 = 0; k2 < 16; k2++) {
            float4 fa = *(const float4*)&As[k2][ty * 4];
            float4 fb = *(const float4*)&Bs[k2][tx * 4];
            float a[4] = {fa.x, fa.y, fa.z, fa.w};
            float b[4] = {fb.x, fb.y, fb.z, fb.w};
#pragma unroll
            for (int i = 0; i < 4; i++)
#pragma unroll
                for (int j = 0; j < 4; j++)
                    acc[i][j] = fmaf(a[i], b[j], acc[i][j]);
        }
        __syncthreads();
    }
#pragma unroll
    for (int i = 0; i < 4; i++) {
        int t = t0 + ty * 4 + i;
#pragma unroll
        for (int j = 0; j < 4; j++) {
            int n = n0 + tx * 4 + j;
            g_xp[dir][t][n] = acc[i][j] + b1[n] + b2[n];
        }
    }
}

// ---------------- BiLSTM recurrence: 16-CTA DSMEM cluster ---------------
// 32 CTAs, cluster (16,1,1): cluster 0 = fwd, cluster 1 = bwd. 128 thr/CTA.
// CTA rank owns h units rank*16..+15 (64 W_hh rows). Thread (lr=tid>>1,
// half=tid&1) computes one 128-col half-dot of row lr; weights in registers.
// h_buf per-producer [parity][16][20]. Sync protocol identical to proven R6
// (volatile v4 spin over flags + pairwise ld.acquire), one __syncthreads per
// step; warp 0 (lanes 0..15) does activations + DSMEM push + flag release.
__global__ void __cluster_dims__(NCL, 1, 1) __launch_bounds__(128, 1) lstm_kernel(
    const float* __restrict__ Whhf, const float* __restrict__ Whhb,
    const float* __restrict__ h0, const float* __restrict__ c0)
{
    __shared__ __align__(16) float h_buf[2][16][20];
    __shared__ __align__(16) float h_stage[16];
    __shared__ float gate_s[2][64];
    __shared__ __align__(16) unsigned flags[16];

    unsigned rank;
    asm("mov.u32 %0, %%cluster_ctarank;" : "=r"(rank));
    int dir  = blockIdx.x >> 4;
    int tid  = threadIdx.x;
    int lane = tid & 31;
    int lr   = tid >> 1;          // local row 0..63 (= gate*16 + jl)
    int half = tid & 1;           // which 128-col half of the 256-dot
    int gate = lr >> 4;
    int jl   = lr & 15;
    int rowg = gate * 256 + (int)rank * 16 + jl;
    const float* Whh = dir ? Whhb : Whhf;

    // 32 float4 weights in registers (cols half*128 .. +127 of row rowg)
    float4 w[32];
    const float4* wsrc = (const float4*)(Whh + (long long)rowg * 256 + half * 128);
#pragma unroll
    for (int i = 0; i < 32; i++) w[i] = wsrc[i];

    // init h(0), flags, c
    for (int i = tid; i < 256; i += 128)
        h_buf[0][i >> 4][i & 15] = h0[dir * 256 + i];
    if (tid < 16) flags[tid] = 0u;
    float cst = (tid < 16) ? c0[dir * 256 + (int)rank * 16 + tid] : 0.f;
    __syncthreads();
    asm volatile("barrier.cluster.arrive.aligned;" ::: "memory");
    asm volatile("barrier.cluster.wait.aligned;" ::: "memory");

    unsigned flags_sa = sm_addr(flags);
    unsigned hbuf_sa  = sm_addr(h_buf);

    // pushers = warp 0 lanes 0..15: peer CTA = lane; two parity dests
    unsigned dsth0 = 0, dsth1 = 0, dstfl = 0;
    if (tid < 16) {
        unsigned l0 = hbuf_sa + (unsigned)((0 * 16 + (int)rank) * 20) * 4u;
        unsigned l1 = hbuf_sa + (unsigned)((1 * 16 + (int)rank) * 20) * 4u;
        unsigned lf = flags_sa + 4u * rank;
        asm("mapa.shared::cluster.u32 %0, %1, %2;" : "=r"(dsth0) : "r"(l0), "r"((unsigned)tid));
        asm("mapa.shared::cluster.u32 %0, %1, %2;" : "=r"(dsth1) : "r"(l1), "r"((unsigned)tid));
        asm("mapa.shared::cluster.u32 %0, %1, %2;" : "=r"(dstfl) : "r"(lf), "r"((unsigned)tid));
    }

    const float* xbase = &g_xp[dir][0][0];
    float xv = 0.f;
    if (half == 0) xv = __ldcg(xbase + (long long)(dir ? TT - 1 : 0) * 1024 + rowg);

    bool iswarp0 = (tid < 32);

    for (int s = 1; s <= TT; s++) {
        int t = dir ? (TT - s) : (s - 1);
        int par = (s - 1) & 1;

        // ---- wait until all 16 producers published h(s-1) ----
        if (s > 1) {
            unsigned need = (unsigned)(s - 1);
            while (true) {
                unsigned m = 0xffffffffu;
#pragma unroll
                for (int i = 0; i < 4; i++) {
                    unsigned f0, f1, f2, f3;
                    asm volatile("ld.volatile.shared.v4.u32 {%0,%1,%2,%3}, [%4];"
                                 : "=r"(f0), "=r"(f1), "=r"(f2), "=r"(f3)
                                 : "r"(flags_sa + 16u * i));
                    m = min(m, min(min(f0, f1), min(f2, f3)));
                }
                if (m >= need) break;
            }
#pragma unroll
            for (int i = 0; i < 16; i++) {
                unsigned tmpv;
                asm volatile("ld.acquire.cluster.shared::cta.u32 %0, [%1];"
                             : "=r"(tmpv) : "r"(flags_sa + 4u * i) : "memory");
            }
        }

        // ---- half-dot over 8 producer slices (16 floats each) ----
        float a0 = 0.f, a1 = 0.f, a2 = 0.f, a3 = 0.f;
#pragma unroll
        for (int pp = 0; pp < 8; pp++) {
            int p = half * 8 + pp;
            const float4* sp = (const float4*)&h_buf[par][p][0];
            float4 hA = sp[0]; float4 wA = w[pp * 4 + 0];
            a0 = fmaf(wA.x, hA.x, a0); a0 = fmaf(wA.y, hA.y, a0);
            a0 = fmaf(wA.z, hA.z, a0); a0 = fmaf(wA.w, hA.w, a0);
            float4 hB = sp[1]; float4 wB = w[pp * 4 + 1];
            a1 = fmaf(wB.x, hB.x, a1); a1 = fmaf(wB.y, hB.y, a1);
            a1 = fmaf(wB.z, hB.z, a1); a1 = fmaf(wB.w, hB.w, a1);
            float4 hC = sp[2]; float4 wC = w[pp * 4 + 2];
            a2 = fmaf(wC.x, hC.x, a2); a2 = fmaf(wC.y, hC.y, a2);
            a2 = fmaf(wC.z, hC.z, a2); a2 = fmaf(wC.w, hC.w, a2);
            float4 hD = sp[3]; float4 wD = w[pp * 4 + 3];
            a3 = fmaf(wD.x, hD.x, a3); a3 = fmaf(wD.y, hD.y, a3);
            a3 = fmaf(wD.z, hD.z, a3); a3 = fmaf(wD.w, hD.w, a3);
        }
        float sum = (a0 + a1) + (a2 + a3);
        sum += __shfl_xor_sync(0xffffffffu, sum, 1);   // combine the two halves

        // prefetch next step's x while the tail of this step runs
        float xvn = 0.f;
        if (half == 0 && s < TT)
            xvn = __ldcg(xbase + (long long)(dir ? TT - 1 - s : s) * 1024 + rowg);
        if (half == 0) gate_s[s & 1][lr] = sum + xv;
        xv = xvn;
        __syncthreads();   // orders all h_buf(par) reads; gate_s[s&1] complete

        // ---- warp 0: activations, state, push, release ----
        if (iswarp0) {
            if (lane < 16) {
                float gi = gate_s[s & 1][lane];
                float gf = gate_s[s & 1][16 + lane];
                float gg = gate_s[s & 1][32 + lane];
                float go = gate_s[s & 1][48 + lane];
                gi = __fdividef(1.f, 1.f + __expf(-gi));
                gf = __fdividef(1.f, 1.f + __expf(-gf));
                go = __fdividef(1.f, 1.f + __expf(-go));
                gg = __fdividef(2.f, 1.f + __expf(-2.f * gg)) - 1.f;   // tanh
                cst = gf * cst + gi * gg;
                float hv = go * (__fdividef(2.f, 1.f + __expf(-2.f * cst)) - 1.f);
                h_stage[lane] = hv;
                __stcg(&g_lstm[(long long)t * 512 + dir * 256 + (int)rank * 16 + lane], hv);
            }
            __syncwarp();
            if (lane < 16) {
                unsigned dh = (s & 1) ? dsth1 : dsth0;
                const float4* st4 = (const float4*)h_stage;
#pragma unroll
                for (int i = 0; i < 4; i++) {
                    float4 v = st4[i];
                    asm volatile("st.shared::cluster.v4.f32 [%0], {%1,%2,%3,%4};"
                                 :: "r"(dh + 16u * i),
                                    "f"(v.x), "f"(v.y), "f"(v.z), "f"(v.w) : "memory");
                }
                asm volatile("st.release.cluster.shared::cluster.u32 [%0], %1;"
                             :: "r"(dstfl), "r"((unsigned)s) : "memory");
            }
        }
        // warps 1..3 fall through into the next step's spin
    }
}

// ---------------- logits = lstm_out @ W_out.T + b_out --------------------
__global__ void __launch_bounds__(256) logits_kernel(
    const float* __restrict__ Wout, const float* __restrict__ bout)
{
    __shared__ float Ws[7 * 512];
    int tid = threadIdx.x;
    for (int i = tid; i < 7 * 512; i += 256) Ws[i] = Wout[i];
    __syncthreads();

    int t = blockIdx.x * 8 + (tid >> 5);
    int lane = tid & 31;
    float acc[7];
#pragma unroll
    for (int j = 0; j < 7; j++) acc[j] = 0.f;
#pragma unroll
    for (int i = 0; i < 16; i++) {
        int k = lane + 32 * i;
        float v = g_lstm[(long long)t * 512 + k];
#pragma unroll
        for (int j = 0; j < 7; j++)
            acc[j] = fmaf(v, Ws[j * 512 + k], acc[j]);
    }
#pragma unroll
    for (int j = 0; j < 7; j++)
#pragma unroll
        for (int o = 16; o > 0; o >>= 1)
            acc[j] += __shfl_xor_sync(0xffffffffu, acc[j], o);
    if (lane < 7) g_logits[t * 8 + lane] = acc[lane] + bout[lane];
    else if (lane == 7) g_logits[t * 8 + 7] = 0.f;
}

// ---------------- Viterbi: replicated-fv, feats preloaded to registers ---
__global__ void viterbi_kernel(const float* __restrict__ trans,
                               float* __restrict__ out, int out_size)
{
    __shared__ unsigned bp_s[TT];
    __shared__ __align__(16) float feat_s[2][32][8];

    int lane = threadIdx.x;
    int n = (lane < 7) ? lane : 0;           // each lane owns target tag n
    float tn[7], tsp[7], f[7];
#pragma unroll
    for (int p = 0; p < 7; p++) tn[p] = trans[n * 7 + p];
#pragma unroll
    for (int p = 0; p < 7; p++) tsp[p] = trans[6 * 7 + p];   // STOP row
#pragma unroll
    for (int p = 0; p < 7; p++) f[p] = (p == 5) ? 0.f : -10000.f;  // START=5

    float4 p0 = *(const float4*)&g_logits[lane * 8];
    float4 p1 = *(const float4*)&g_logits[lane * 8 + 4];
    *(float4*)&feat_s[0][lane][0] = p0;
    *(float4*)&feat_s[0][lane][4] = p1;
    __syncwarp();

    for (int tile = 0; tile < TT / 32; tile++) {
        int buf = tile & 1;
        if (tile < TT / 32 - 1) {
            const float* src = &g_logits[((tile + 1) * 32 + lane) * 8];
            p0 = *(const float4*)src;
            p1 = *(const float4*)(src + 4);
        }
        // preload this lane's feat column into registers (off the chain)
        float fr[32];
#pragma unroll
        for (int i = 0; i < 32; i++) fr[i] = feat_s[buf][i][n];
#pragma unroll
        for (int s2 = 0; s2 < 32; s2++) {
            int t = tile * 32 + s2;
            float c[7];
#pragma unroll
            for (int p = 0; p < 7; p++) c[p] = f[p] + tn[p];
            float m01 = fmaxf(c[0], c[1]), m23 = fmaxf(c[2], c[3]);
            float m45 = fmaxf(c[4], c[5]);
            float m = fmaxf(fmaxf(m01, m23), fmaxf(m45, c[6]));
            // first-index argmax (exact equality; m is bitwise one of c[p])
            int bi = 6;
            bi = (c[5] == m) ? 5 : bi;
            bi = (c[4] == m) ? 4 : bi;
            bi = (c[3] == m) ? 3 : bi;
            bi = (c[2] == m) ? 2 : bi;
            bi = (c[1] == m) ? 1 : bi;
            bi = (c[0] == m) ? 0 : bi;
            float fnew = m + fr[s2];
#pragma unroll
            for (int p = 0; p < 7; p++) f[p] = __shfl_sync(0xffffffffu, fnew, p);
            unsigned contrib = (lane < 7) ? ((unsigned)bi << (3 * lane)) : 0u;
            unsigned word = __reduce_or_sync(0xffffffffu, contrib);
            if (lane == 0) bp_s[t] = word;
        }
        __syncwarp();
        if (tile < TT / 32 - 1) {
            *(float4*)&feat_s[buf ^ 1][lane][0] = p0;
            *(float4*)&feat_s[buf ^ 1][lane][4] = p1;
        }
        __syncwarp();
    }

    // termination (replicated in every lane)
    float tm[7];
#pragma unroll
    for (int p = 0; p < 7; p++) tm[p] = f[p] + tsp[p];
    float m01 = fmaxf(tm[0], tm[1]), m23 = fmaxf(tm[2], tm[3]);
    float m45 = fmaxf(tm[4], tm[5]);
    float bestv = fmaxf(fmaxf(m01, m23), fmaxf(m45, tm[6]));
    int bestn = 6;
    bestn = (tm[5] == bestv) ? 5 : bestn;
    bestn = (tm[4] == bestv) ? 4 : bestn;
    bestn = (tm[3] == bestv) ? 3 : bestn;
    bestn = (tm[2] == bestv) ? 2 : bestn;
    bestn = (tm[1] == bestv) ? 1 : bestn;
    bestn = (tm[0] == bestv) ? 0 : bestn;

    for (int i = 1 + TT + lane; i < out_size; i += 32) out[i] = 0.f;
    if (lane == 0) {
        out[0] = bestv;
        int tag = bestn;
        for (int t = TT - 1; t >= 0; t--) {
            out[1 + t] = (float)tag;
            tag = (int)((bp_s[t] >> (3 * tag)) & 7u);
        }
    }
}

// ---------------- launch ---------------------------------------------------
extern "C" void kernel_launch(void* const* d_in, const int* in_sizes, int n_in,
                              void* d_out, int out_size)
{
    const int*   sent  = (const int*)d_in[0];
    const float* emb   = (const float*)d_in[1];
    const float* Wihf  = (const float*)d_in[2];
    const float* Whhf  = (const float*)d_in[3];
    const float* bihf  = (const float*)d_in[4];
    const float* bhhf  = (const float*)d_in[5];
    const float* Wihb  = (const float*)d_in[6];
    const float* Whhb  = (const float*)d_in[7];
    const float* bihb  = (const float*)d_in[8];
    const float* bhhb  = (const float*)d_in[9];
    const float* h0    = (const float*)d_in[10];
    const float* c0    = (const float*)d_in[11];
    const float* Wout  = (const float*)d_in[12];
    const float* bout  = (const float*)d_in[13];
    const float* trans = (const float*)d_in[14];
    float* out = (float*)d_out;

    // allow 16-CTA (non-portable) clusters; idempotent, capture-safe
    cudaFuncSetAttribute(lstm_kernel,
                         cudaFuncAttributeNonPortableClusterSizeAllowed, 1);

    xproj_kernel<<<dim3(TT / 64, 1024 / 64, 2), 256>>>(
        sent, emb, Wihf, bihf, bhhf, Wihb, bihb, bhhb);
    lstm_kernel<<<2 * NCL, 128>>>(Whhf, Whhb, h0, c0);
    logits_kernel<<<TT / 8, 256>>>(Wout, bout);
    viterbi_kernel<<<1, 32>>>(trans, out, out_size);
}

// round 9
// speedup vs baseline: 1.2805x; 1.1940x over previous
#include <cuda_runtime.h>
#include <math.h>

#define TT 8192
#define NCL 16    // CTAs per direction (= cluster size) in the LSTM kernel

// ---------------- scratch (static device globals; no allocation) ----------
__device__ float g_xp[2][TT][1024];   // gate preactivations x@W_ih.T + b_ih + b_hh
__device__ float g_lstm[TT * 512];    // [T][512] = concat(hf, hb)
__device__ float g_logits[TT * 8];    // [T][8] padded (7 used)

__device__ __forceinline__ unsigned sm_addr(const void* p) {
    return (unsigned)__cvta_generic_to_shared(p);
}

__device__ __forceinline__ float tanh_ap(float x) {
    float y;
    asm("tanh.approx.f32 %0, %1;" : "=f"(y) : "f"(x));
    return y;
}
// sigmoid(x) = 0.5*tanh(0.5x) + 0.5  (single MUFU on the chain)
__device__ __forceinline__ float sig_ap(float x) {
    return fmaf(0.5f, tanh_ap(0.5f * x), 0.5f);
}

// ---------------- x_proj GEMM: C[t][n] = emb[sent[t]] . W[n] + b1[n]+b2[n]
__global__ void __launch_bounds__(256) xproj_kernel(
    const int* __restrict__ sent, const float* __restrict__ emb,
    const float* __restrict__ Wf, const float* __restrict__ b1f, const float* __restrict__ b2f,
    const float* __restrict__ Wb, const float* __restrict__ b1b, const float* __restrict__ b2b)
{
    int dir = blockIdx.z;
    const float* W  = dir ? Wb  : Wf;
    const float* b1 = dir ? b1b : b1f;
    const float* b2 = dir ? b2b : b2f;
    int t0 = blockIdx.x * 64;
    int n0 = blockIdx.y * 64;

    __shared__ __align__(16) float As[16][68];
    __shared__ __align__(16) float Bs[16][68];
    __shared__ int sent_s[64];

    int tid = threadIdx.x;
    if (tid < 64) sent_s[tid] = sent[t0 + tid];
    __syncthreads();

    int tx = tid & 15;
    int ty = tid >> 4;
    float acc[4][4];
#pragma unroll
    for (int i = 0; i < 4; i++)
#pragma unroll
        for (int j = 0; j < 4; j++) acc[i][j] = 0.f;

    int kk = tid & 15;
    int m0 = tid >> 4;
    for (int k0 = 0; k0 < 256; k0 += 16) {
#pragma unroll
        for (int r = 0; r < 4; r++) {
            int mm = m0 + 16 * r;
            As[kk][mm] = emb[(long long)sent_s[mm] * 256 + k0 + kk];
            Bs[kk][mm] = W[(long long)(n0 + mm) * 256 + k0 + kk];
        }
        __syncthreads();
#pragma unroll
        for (int k2 = 0; k2 < 16; k2++) {
            float4 fa = *(const float4*)&As[k2][ty * 4];
            float4 fb = *(const float4*)&Bs[k2][tx * 4];
            float a[4] = {fa.x, fa.y, fa.z, fa.w};
            float b[4] = {fb.x, fb.y, fb.z, fb.w};
#pragma unroll
            for (int i = 0; i < 4; i++)
#pragma unroll
                for (int j = 0; j < 4; j++)
                    acc[i][j] = fmaf(a[i], b[j], acc[i][j]);
        }
        __syncthreads();
    }
#pragma unroll
    for (int i = 0; i < 4; i++) {
        int t = t0 + ty * 4 + i;
#pragma unroll
        for (int j = 0; j < 4; j++) {
            int n = n0 + tx * 4 + j;
            g_xp[dir][t][n] = acc[i][j] + b1[n] + b2[n];
        }
    }
}

// ---------------- BiLSTM recurrence: 16-CTA DSMEM cluster ---------------
// Structure identical to the passing R8 kernel; changes: MUFU tanh
// activations (chain ~50 cyc vs ~170) and depth-2 x prefetch issued BEFORE
// the flag poll (g_xp is read-only; the load has no loop dependency).
__global__ void __cluster_dims__(NCL, 1, 1) __launch_bounds__(128, 1) lstm_kernel(
    const float* __restrict__ Whhf, const float* __restrict__ Whhb,
    const float* __restrict__ h0, const float* __restrict__ c0)
{
    __shared__ __align__(16) float h_buf[2][16][20];
    __shared__ __align__(16) float h_stage[16];
    __shared__ float gate_s[2][64];
    __shared__ __align__(16) unsigned flags[16];

    unsigned rank;
    asm("mov.u32 %0, %%cluster_ctarank;" : "=r"(rank));
    int dir  = blockIdx.x >> 4;
    int tid  = threadIdx.x;
    int lane = tid & 31;
    int lr   = tid >> 1;          // local row 0..63 (= gate*16 + jl)
    int half = tid & 1;           // which 128-col half of the 256-dot
    int gate = lr >> 4;
    int jl   = lr & 15;
    int rowg = gate * 256 + (int)rank * 16 + jl;
    const float* Whh = dir ? Whhb : Whhf;

    // 32 float4 weights in registers (cols half*128 .. +127 of row rowg)
    float4 w[32];
    const float4* wsrc = (const float4*)(Whh + (long long)rowg * 256 + half * 128);
#pragma unroll
    for (int i = 0; i < 32; i++) w[i] = wsrc[i];

    // init h(0), flags, c
    for (int i = tid; i < 256; i += 128)
        h_buf[0][i >> 4][i & 15] = h0[dir * 256 + i];
    if (tid < 16) flags[tid] = 0u;
    float cst = (tid < 16) ? c0[dir * 256 + (int)rank * 16 + tid] : 0.f;
    __syncthreads();
    asm volatile("barrier.cluster.arrive.aligned;" ::: "memory");
    asm volatile("barrier.cluster.wait.aligned;" ::: "memory");

    unsigned flags_sa = sm_addr(flags);
    unsigned hbuf_sa  = sm_addr(h_buf);

    // pushers = warp 0 lanes 0..15: peer CTA = lane; two parity dests
    unsigned dsth0 = 0, dsth1 = 0, dstfl = 0;
    if (tid < 16) {
        unsigned l0 = hbuf_sa + (unsigned)((0 * 16 + (int)rank) * 20) * 4u;
        unsigned l1 = hbuf_sa + (unsigned)((1 * 16 + (int)rank) * 20) * 4u;
        unsigned lf = flags_sa + 4u * rank;
        asm("mapa.shared::cluster.u32 %0, %1, %2;" : "=r"(dsth0) : "r"(l0), "r"((unsigned)tid));
        asm("mapa.shared::cluster.u32 %0, %1, %2;" : "=r"(dsth1) : "r"(l1), "r"((unsigned)tid));
        asm("mapa.shared::cluster.u32 %0, %1, %2;" : "=r"(dstfl) : "r"(lf), "r"((unsigned)tid));
    }

    const float* xbase = &g_xp[dir][0][0];
    // depth-2 prefetch: xv = x(step s), xv1 = x(step s+1)
    float xv = 0.f, xv1 = 0.f;
    if (half == 0) {
        xv  = __ldcg(xbase + (long long)(dir ? TT - 1 : 0) * 1024 + rowg);
        xv1 = __ldcg(xbase + (long long)(dir ? TT - 2 : 1) * 1024 + rowg);
    }

    bool iswarp0 = (tid < 32);

    for (int s = 1; s <= TT; s++) {
        int t = dir ? (TT - s) : (s - 1);
        int par = (s - 1) & 1;

        // issue prefetch for step s+2 FIRST (no dependency on flags)
        float xv2 = 0.f;
        if (half == 0 && s + 2 <= TT) {
            int tn2 = dir ? (TT - s - 2) : (s + 1);
            xv2 = __ldcg(xbase + (long long)tn2 * 1024 + rowg);
        }

        // ---- wait until all 16 producers published h(s-1) ----
        if (s > 1) {
            unsigned need = (unsigned)(s - 1);
            while (true) {
                unsigned m = 0xffffffffu;
#pragma unroll
                for (int i = 0; i < 4; i++) {
                    unsigned f0, f1, f2, f3;
                    asm volatile("ld.volatile.shared.v4.u32 {%0,%1,%2,%3}, [%4];"
                                 : "=r"(f0), "=r"(f1), "=r"(f2), "=r"(f3)
                                 : "r"(flags_sa + 16u * i));
                    m = min(m, min(min(f0, f1), min(f2, f3)));
                }
                if (m >= need) break;
            }
#pragma unroll
            for (int i = 0; i < 16; i++) {
                unsigned tmpv;
                asm volatile("ld.acquire.cluster.shared::cta.u32 %0, [%1];"
                             : "=r"(tmpv) : "r"(flags_sa + 4u * i) : "memory");
            }
        }

        // ---- half-dot over 8 producer slices (16 floats each) ----
        float a0 = 0.f, a1 = 0.f, a2 = 0.f, a3 = 0.f;
#pragma unroll
        for (int pp = 0; pp < 8; pp++) {
            int p = half * 8 + pp;
            const float4* sp = (const float4*)&h_buf[par][p][0];
            float4 hA = sp[0]; float4 wA = w[pp * 4 + 0];
            a0 = fmaf(wA.x, hA.x, a0); a0 = fmaf(wA.y, hA.y, a0);
            a0 = fmaf(wA.z, hA.z, a0); a0 = fmaf(wA.w, hA.w, a0);
            float4 hB = sp[1]; float4 wB = w[pp * 4 + 1];
            a1 = fmaf(wB.x, hB.x, a1); a1 = fmaf(wB.y, hB.y, a1);
            a1 = fmaf(wB.z, hB.z, a1); a1 = fmaf(wB.w, hB.w, a1);
            float4 hC = sp[2]; float4 wC = w[pp * 4 + 2];
            a2 = fmaf(wC.x, hC.x, a2); a2 = fmaf(wC.y, hC.y, a2);
            a2 = fmaf(wC.z, hC.z, a2); a2 = fmaf(wC.w, hC.w, a2);
            float4 hD = sp[3]; float4 wD = w[pp * 4 + 3];
            a3 = fmaf(wD.x, hD.x, a3); a3 = fmaf(wD.y, hD.y, a3);
            a3 = fmaf(wD.z, hD.z, a3); a3 = fmaf(wD.w, hD.w, a3);
        }
        float sum = (a0 + a1) + (a2 + a3);
        sum += __shfl_xor_sync(0xffffffffu, sum, 1);   // combine the two halves

        if (half == 0) gate_s[s & 1][lr] = sum + xv;
        xv = xv1; xv1 = xv2;
        __syncthreads();   // orders all h_buf(par) reads; gate_s[s&1] complete

        // ---- warp 0: activations (MUFU tanh), state, push, release ----
        if (iswarp0) {
            if (lane < 16) {
                float gi = sig_ap(gate_s[s & 1][lane]);
                float gf = sig_ap(gate_s[s & 1][16 + lane]);
                float gg = tanh_ap(gate_s[s & 1][32 + lane]);
                float go = sig_ap(gate_s[s & 1][48 + lane]);
                cst = gf * cst + gi * gg;
                float hv = go * tanh_ap(cst);
                h_stage[lane] = hv;
                __stcg(&g_lstm[(long long)t * 512 + dir * 256 + (int)rank * 16 + lane], hv);
            }
            __syncwarp();
            if (lane < 16) {
                unsigned dh = (s & 1) ? dsth1 : dsth0;
                const float4* st4 = (const float4*)h_stage;
#pragma unroll
                for (int i = 0; i < 4; i++) {
                    float4 v = st4[i];
                    asm volatile("st.shared::cluster.v4.f32 [%0], {%1,%2,%3,%4};"
                                 :: "r"(dh + 16u * i),
                                    "f"(v.x), "f"(v.y), "f"(v.z), "f"(v.w) : "memory");
                }
                asm volatile("st.release.cluster.shared::cluster.u32 [%0], %1;"
                             :: "r"(dstfl), "r"((unsigned)s) : "memory");
            }
        }
        // warps 1..3 fall through into the next step's spin
    }
}

// ---------------- logits = lstm_out @ W_out.T + b_out --------------------
__global__ void __launch_bounds__(256) logits_kernel(
    const float* __restrict__ Wout, const float* __restrict__ bout)
{
    __shared__ float Ws[7 * 512];
    int tid = threadIdx.x;
    for (int i = tid; i < 7 * 512; i += 256) Ws[i] = Wout[i];
    __syncthreads();

    int t = blockIdx.x * 8 + (tid >> 5);
    int lane = tid & 31;
    float acc[7];
#pragma unroll
    for (int j = 0; j < 7; j++) acc[j] = 0.f;
#pragma unroll
    for (int i = 0; i < 16; i++) {
        int k = lane + 32 * i;
        float v = g_lstm[(long long)t * 512 + k];
#pragma unroll
        for (int j = 0; j < 7; j++)
            acc[j] = fmaf(v, Ws[j * 512 + k], acc[j]);
    }
#pragma unroll
    for (int j = 0; j < 7; j++)
#pragma unroll
        for (int o = 16; o > 0; o >>= 1)
            acc[j] += __shfl_xor_sync(0xffffffffu, acc[j], o);
    if (lane < 7) g_logits[t * 8 + lane] = acc[lane] + bout[lane];
    else if (lane == 7) g_logits[t * 8 + 7] = 0.f;
}

// ---------------- Viterbi: replicated-fv; bp emission off the chain ------
__global__ void viterbi_kernel(const float* __restrict__ trans,
                               float* __restrict__ out, int out_size)
{
    __shared__ unsigned bp_s[TT];
    __shared__ __align__(16) float feat_s[2][32][8];

    int lane = threadIdx.x;
    int n = (lane < 7) ? lane : 0;           // each lane owns target tag n
    float tn[7], tsp[7], f[7];
#pragma unroll
    for (int p = 0; p < 7; p++) tn[p] = trans[n * 7 + p];
#pragma unroll
    for (int p = 0; p < 7; p++) tsp[p] = trans[6 * 7 + p];   // STOP row
#pragma unroll
    for (int p = 0; p < 7; p++) f[p] = (p == 5) ? 0.f : -10000.f;  // START=5

    float4 p0 = *(const float4*)&g_logits[lane * 8];
    float4 p1 = *(const float4*)&g_logits[lane * 8 + 4];
    *(float4*)&feat_s[0][lane][0] = p0;
    *(float4*)&feat_s[0][lane][4] = p1;
    __syncwarp();

    for (int tile = 0; tile < TT / 32; tile++) {
        int buf = tile & 1;
        if (tile < TT / 32 - 1) {
            const float* src = &g_logits[((tile + 1) * 32 + lane) * 8];
            p0 = *(const float4*)src;
            p1 = *(const float4*)(src + 4);
        }
        // preload this lane's feat column into registers (off the chain)
        float fr[32];
#pragma unroll
        for (int i = 0; i < 32; i++) fr[i] = feat_s[buf][i][n];

        // per-lane packed backpointers for this tile (3 bits x 8 per word)
        unsigned bw[4] = {0u, 0u, 0u, 0u};
#pragma unroll
        for (int s2 = 0; s2 < 32; s2++) {
            float c[7];
#pragma unroll
            for (int p = 0; p < 7; p++) c[p] = f[p] + tn[p];
            float m01 = fmaxf(c[0], c[1]), m23 = fmaxf(c[2], c[3]);
            float m45 = fmaxf(c[4], c[5]);
            float m = fmaxf(fmaxf(m01, m23), fmaxf(m45, c[6]));
            // first-index argmax (exact equality; m is bitwise one of c[p])
            int bi = 6;
            bi = (c[5] == m) ? 5 : bi;
            bi = (c[4] == m) ? 4 : bi;
            bi = (c[3] == m) ? 3 : bi;
            bi = (c[2] == m) ? 2 : bi;
            bi = (c[1] == m) ? 1 : bi;
            bi = (c[0] == m) ? 0 : bi;
            float fnew = m + fr[s2];
#pragma unroll
            for (int p = 0; p < 7; p++) f[p] = __shfl_sync(0xffffffffu, fnew, p);
            bw[s2 >> 3] |= (unsigned)bi << (3 * (s2 & 7));   // off-chain
        }
        // emit the tile's 32 packed bp words (off the serial chain)
#pragma unroll
        for (int s2 = 0; s2 < 32; s2++) {
            unsigned bi = (bw[s2 >> 3] >> (3 * (s2 & 7))) & 7u;
            unsigned contrib = (lane < 7) ? (bi << (3 * lane)) : 0u;
            unsigned word = __reduce_or_sync(0xffffffffu, contrib);
            if (lane == 0) bp_s[tile * 32 + s2] = word;
        }
        __syncwarp();
        if (tile < TT / 32 - 1) {
            *(float4*)&feat_s[buf ^ 1][lane][0] = p0;
            *(float4*)&feat_s[buf ^ 1][lane][4] = p1;
        }
        __syncwarp();
    }

    // termination (replicated in every lane)
    float tm[7];
#pragma unroll
    for (int p = 0; p < 7; p++) tm[p] = f[p] + tsp[p];
    float m01 = fmaxf(tm[0], tm[1]), m23 = fmaxf(tm[2], tm[3]);
    float m45 = fmaxf(tm[4], tm[5]);
    float bestv = fmaxf(fmaxf(m01, m23), fmaxf(m45, tm[6]));
    int bestn = 6;
    bestn = (tm[5] == bestv) ? 5 : bestn;
    bestn = (tm[4] == bestv) ? 4 : bestn;
    bestn = (tm[3] == bestv) ? 3 : bestn;
    bestn = (tm[2] == bestv) ? 2 : bestn;
    bestn = (tm[1] == bestv) ? 1 : bestn;
    bestn = (tm[0] == bestv) ? 0 : bestn;

    for (int i = 1 + TT + lane; i < out_size; i += 32) out[i] = 0.f;
    if (lane == 0) {
        out[0] = bestv;
        int tag = bestn;
        for (int t = TT - 1; t >= 0; t--) {
            out[1 + t] = (float)tag;
            tag = (int)((bp_s[t] >> (3 * tag)) & 7u);
        }
    }
}

// ---------------- launch ---------------------------------------------------
extern "C" void kernel_launch(void* const* d_in, const int* in_sizes, int n_in,
                              void* d_out, int out_size)
{
    const int*   sent  = (const int*)d_in[0];
    const float* emb   = (const float*)d_in[1];
    const float* Wihf  = (const float*)d_in[2];
    const float* Whhf  = (const float*)d_in[3];
    const float* bihf  = (const float*)d_in[4];
    const float* bhhf  = (const float*)d_in[5];
    const float* Wihb  = (const float*)d_in[6];
    const float* Whhb  = (const float*)d_in[7];
    const float* bihb  = (const float*)d_in[8];
    const float* bhhb  = (const float*)d_in[9];
    const float* h0    = (const float*)d_in[10];
    const float* c0    = (const float*)d_in[11];
    const float* Wout  = (const float*)d_in[12];
    const float* bout  = (const float*)d_in[13];
    const float* trans = (const float*)d_in[14];
    float* out = (float*)d_out;

    // allow 16-CTA (non-portable) clusters; idempotent, capture-safe
    cudaFuncSetAttribute(lstm_kernel,
                         cudaFuncAttributeNonPortableClusterSizeAllowed, 1);

    xproj_kernel<<<dim3(TT / 64, 1024 / 64, 2), 256>>>(
        sent, emb, Wihf, bihf, bhhf, Wihb, bihb, bhhb);
    lstm_kernel<<<2 * NCL, 128>>>(Whhf, Whhb, h0, c0);
    logits_kernel<<<TT / 8, 256>>>(Wout, bout);
    viterbi_kernel<<<1, 32>>>(trans, out, out_size);
}

// round 10
// speedup vs baseline: 1.3366x; 1.0438x over previous
#include <cuda_runtime.h>
#include <math.h>

#define TT 8192
#define NCL 16    // CTAs per direction (= cluster size) in the LSTM kernel

// ---------------- scratch (static device globals; no allocation) ----------
__device__ float g_xp[2][TT][1024];   // gate preactivations x@W_ih.T + b_ih + b_hh
__device__ float g_lstm[TT * 512];    // [T][512] = concat(hf, hb)
__device__ float g_logits[TT * 8];    // [T][8] padded (7 used)
__device__ int   g_done[2][128];      // xproj watermark: blocks finished per t-tile

__device__ __forceinline__ unsigned sm_addr(const void* p) {
    return (unsigned)__cvta_generic_to_shared(p);
}
__device__ __forceinline__ float tanh_ap(float x) {
    float y;
    asm("tanh.approx.f32 %0, %1;" : "=f"(y) : "f"(x));
    return y;
}
__device__ __forceinline__ float sig_ap(float x) {
    return fmaf(0.5f, tanh_ap(0.5f * x), 0.5f);
}

// ---------------- watermark reset (graph replays reuse counters) ----------
__global__ void reset_done_kernel() {
    if (threadIdx.x < 256) ((int*)g_done)[threadIdx.x] = 0;
}

// ---------------- x_proj GEMM: C[t][n] = emb[sent[t]] . W[n] + b1[n]+b2[n]
// dir 0 fills t-tiles ascending, dir 1 descending (consumption order).
__global__ void __launch_bounds__(256) xproj_kernel(
    const int* __restrict__ sent, const float* __restrict__ emb,
    const float* __restrict__ Wf, const float* __restrict__ b1f, const float* __restrict__ b2f,
    const float* __restrict__ Wb, const float* __restrict__ b1b, const float* __restrict__ b2b)
{
    int dir = blockIdx.z;
    const float* W  = dir ? Wb  : Wf;
    const float* b1 = dir ? b1b : b1f;
    const float* b2 = dir ? b2b : b2f;
    int ttile = dir ? (127 - (int)blockIdx.x) : (int)blockIdx.x;
    int t0 = ttile * 64;
    int n0 = blockIdx.y * 64;

    __shared__ __align__(16) float As[16][68];
    __shared__ __align__(16) float Bs[16][68];
    __shared__ int sent_s[64];

    int tid = threadIdx.x;
    if (tid < 64) sent_s[tid] = sent[t0 + tid];
    __syncthreads();

    int tx = tid & 15;
    int ty = tid >> 4;
    float acc[4][4];
#pragma unroll
    for (int i = 0; i < 4; i++)
#pragma unroll
        for (int j = 0; j < 4; j++) acc[i][j] = 0.f;

    int kk = tid & 15;
    int m0 = tid >> 4;
    for (int k0 = 0; k0 < 256; k0 += 16) {
#pragma unroll
        for (int r = 0; r < 4; r++) {
            int mm = m0 + 16 * r;
            As[kk][mm] = emb[(long long)sent_s[mm] * 256 + k0 + kk];
            Bs[kk][mm] = W[(long long)(n0 + mm) * 256 + k0 + kk];
        }
        __syncthreads();
#pragma unroll
        for (int k2 = 0; k2 < 16; k2++) {
            float4 fa = *(const float4*)&As[k2][ty * 4];
            float4 fb = *(const float4*)&Bs[k2][tx * 4];
            float a[4] = {fa.x, fa.y, fa.z, fa.w};
            float b[4] = {fb.x, fb.y, fb.z, fb.w};
#pragma unroll
            for (int i = 0; i < 4; i++)
#pragma unroll
                for (int j = 0; j < 4; j++)
                    acc[i][j] = fmaf(a[i], b[j], acc[i][j]);
        }
        __syncthreads();
    }
#pragma unroll
    for (int i = 0; i < 4; i++) {
        int t = t0 + ty * 4 + i;
#pragma unroll
        for (int j = 0; j < 4; j++) {
            int n = n0 + tx * 4 + j;
            g_xp[dir][t][n] = acc[i][j] + b1[n] + b2[n];
        }
    }
    // publish: all stores globally visible, then count this block
    __threadfence();
    __syncthreads();
    if (tid == 0) atomicAdd(&g_done[dir][ttile], 1);
}

// ---------------- BiLSTM recurrence: 16-CTA DSMEM cluster ---------------
// R9 structure + (a) all-4-gates-of-a-unit in one warp (shfl gather, act
// per-warp pre-barrier, gate_s eliminated), (b) watermark spin before each
// x prefetch tile crossing (xproj runs concurrently on a side stream).
// Arithmetic bit-identical to R9.
__global__ void __cluster_dims__(NCL, 1, 1) __launch_bounds__(128, 1) lstm_kernel(
    const float* __restrict__ Whhf, const float* __restrict__ Whhb,
    const float* __restrict__ h0, const float* __restrict__ c0)
{
    __shared__ __align__(16) float h_buf[2][16][20];
    __shared__ __align__(16) float h_stage[16];
    __shared__ __align__(16) unsigned flags[16];

    unsigned rank;
    asm("mov.u32 %0, %%cluster_ctarank;" : "=r"(rank));
    int dir  = blockIdx.x >> 4;
    int tid  = threadIdx.x;
    int w    = tid >> 5;
    int lane = tid & 31;
    int gate = lane >> 3;         // 0..3
    int ju   = (lane >> 1) & 3;   // unit within warp's 4
    int half = lane & 1;          // which 128-col half of the 256-dot
    int rowg = gate * 256 + (int)rank * 16 + w * 4 + ju;
    const float* Whh = dir ? Whhb : Whhf;

    // 32 float4 weights in registers (cols half*128 .. +127 of row rowg)
    float4 wreg[32];
    const float4* wsrc = (const float4*)(Whh + (long long)rowg * 256 + half * 128);
#pragma unroll
    for (int i = 0; i < 32; i++) wreg[i] = wsrc[i];

    // init h(0), flags, c
    for (int i = tid; i < 256; i += 128)
        h_buf[0][i >> 4][i & 15] = h0[dir * 256 + i];
    if (tid < 16) flags[tid] = 0u;
    float cst = (lane < 4) ? c0[dir * 256 + (int)rank * 16 + w * 4 + lane] : 0.f;
    __syncthreads();
    asm volatile("barrier.cluster.arrive.aligned;" ::: "memory");
    asm volatile("barrier.cluster.wait.aligned;" ::: "memory");

    unsigned flags_sa = sm_addr(flags);
    unsigned hbuf_sa  = sm_addr(h_buf);

    // pushers = warp 0 lanes 0..15: peer CTA = lane; two parity dests
    unsigned dsth0 = 0, dsth1 = 0, dstfl = 0;
    if (tid < 16) {
        unsigned l0 = hbuf_sa + (unsigned)((0 * 16 + (int)rank) * 20) * 4u;
        unsigned l1 = hbuf_sa + (unsigned)((1 * 16 + (int)rank) * 20) * 4u;
        unsigned lf = flags_sa + 4u * rank;
        asm("mapa.shared::cluster.u32 %0, %1, %2;" : "=r"(dsth0) : "r"(l0), "r"((unsigned)tid));
        asm("mapa.shared::cluster.u32 %0, %1, %2;" : "=r"(dsth1) : "r"(l1), "r"((unsigned)tid));
        asm("mapa.shared::cluster.u32 %0, %1, %2;" : "=r"(dstfl) : "r"(lf), "r"((unsigned)tid));
    }

    const float* xbase = &g_xp[dir][0][0];
    int cur_tile = -1;
    // depth-2 prefetch with watermark gating
    float xv = 0.f, xv1 = 0.f;
    if (half == 0) {
        int ta = dir ? TT - 1 : 0;
        int tb = dir ? TT - 2 : 1;
        int tla = ta >> 6;
        if (tla != cur_tile) {
            while (*(volatile int*)&g_done[dir][tla] < 16) { }
            cur_tile = tla;
        }
        xv  = __ldcg(xbase + (long long)ta * 1024 + rowg);
        int tlb = tb >> 6;
        if (tlb != cur_tile) {
            while (*(volatile int*)&g_done[dir][tlb] < 16) { }
            cur_tile = tlb;
        }
        xv1 = __ldcg(xbase + (long long)tb * 1024 + rowg);
    }

    for (int s = 1; s <= TT; s++) {
        int t = dir ? (TT - s) : (s - 1);
        int par = (s - 1) & 1;

        // prefetch x for step s+2 FIRST (watermark-gated, no flag dependency)
        float xv2 = 0.f;
        if (half == 0 && s + 2 <= TT) {
            int tn2 = dir ? (TT - s - 2) : (s + 1);
            int tl2 = tn2 >> 6;
            if (tl2 != cur_tile) {
                while (*(volatile int*)&g_done[dir][tl2] < 16) { }
                cur_tile = tl2;
            }
            xv2 = __ldcg(xbase + (long long)tn2 * 1024 + rowg);
        }

        // ---- wait until all 16 producers published h(s-1) ----
        if (s > 1) {
            unsigned need = (unsigned)(s - 1);
            while (true) {
                unsigned m = 0xffffffffu;
#pragma unroll
                for (int i = 0; i < 4; i++) {
                    unsigned f0, f1, f2, f3;
                    asm volatile("ld.volatile.shared.v4.u32 {%0,%1,%2,%3}, [%4];"
                                 : "=r"(f0), "=r"(f1), "=r"(f2), "=r"(f3)
                                 : "r"(flags_sa + 16u * i));
                    m = min(m, min(min(f0, f1), min(f2, f3)));
                }
                if (m >= need) break;
            }
#pragma unroll
            for (int i = 0; i < 16; i++) {
                unsigned tmpv;
                asm volatile("ld.acquire.cluster.shared::cta.u32 %0, [%1];"
                             : "=r"(tmpv) : "r"(flags_sa + 4u * i) : "memory");
            }
        }

        // ---- half-dot over 8 producer slices (16 floats each) ----
        float a0 = 0.f, a1 = 0.f, a2 = 0.f, a3 = 0.f;
#pragma unroll
        for (int pp = 0; pp < 8; pp++) {
            int p = half * 8 + pp;
            const float4* sp = (const float4*)&h_buf[par][p][0];
            float4 hA = sp[0]; float4 wA = wreg[pp * 4 + 0];
            a0 = fmaf(wA.x, hA.x, a0); a0 = fmaf(wA.y, hA.y, a0);
            a0 = fmaf(wA.z, hA.z, a0); a0 = fmaf(wA.w, hA.w, a0);
            float4 hB = sp[1]; float4 wB = wreg[pp * 4 + 1];
            a1 = fmaf(wB.x, hB.x, a1); a1 = fmaf(wB.y, hB.y, a1);
            a1 = fmaf(wB.z, hB.z, a1); a1 = fmaf(wB.w, hB.w, a1);
            float4 hC = sp[2]; float4 wC = wreg[pp * 4 + 2];
            a2 = fmaf(wC.x, hC.x, a2); a2 = fmaf(wC.y, hC.y, a2);
            a2 = fmaf(wC.z, hC.z, a2); a2 = fmaf(wC.w, hC.w, a2);
            float4 hD = sp[3]; float4 wD = wreg[pp * 4 + 3];
            a3 = fmaf(wD.x, hD.x, a3); a3 = fmaf(wD.y, hD.y, a3);
            a3 = fmaf(wD.z, hD.z, a3); a3 = fmaf(wD.w, hD.w, a3);
        }
        float sum = (a0 + a1) + (a2 + a3);
        sum += __shfl_xor_sync(0xffffffffu, sum, 1);   // combine the two halves
        float g = sum + xv;            // full gate preact valid on even lanes
        xv = xv1; xv1 = xv2;

        // ---- in-warp gate gather + activations (lanes 0..3 own units) ----
        int sb = 2 * (lane & 3);
        float gi = __shfl_sync(0xffffffffu, g, sb);
        float gf = __shfl_sync(0xffffffffu, g, 8 + sb);
        float gg = __shfl_sync(0xffffffffu, g, 16 + sb);
        float go = __shfl_sync(0xffffffffu, g, 24 + sb);
        if (lane < 4) {
            gi = sig_ap(gi); gf = sig_ap(gf); go = sig_ap(go);
            gg = tanh_ap(gg);
            cst = gf * cst + gi * gg;
            float hv = go * tanh_ap(cst);
            h_stage[w * 4 + lane] = hv;
            __stcg(&g_lstm[(long long)t * 512 + dir * 256 + (int)rank * 16 + w * 4 + lane], hv);
        }
        __syncthreads();   // h_stage complete; orders all h_buf(par) reads

        // ---- warp 0 lanes 0..15: push CTA's 16 h values, release flag ----
        if (tid < 16) {
            unsigned dh = (s & 1) ? dsth1 : dsth0;
            const float4* st4 = (const float4*)h_stage;
#pragma unroll
            for (int i = 0; i < 4; i++) {
                float4 v = st4[i];
                asm volatile("st.shared::cluster.v4.f32 [%0], {%1,%2,%3,%4};"
                             :: "r"(dh + 16u * i),
                                "f"(v.x), "f"(v.y), "f"(v.z), "f"(v.w) : "memory");
            }
            asm volatile("st.release.cluster.shared::cluster.u32 [%0], %1;"
                         :: "r"(dstfl), "r"((unsigned)s) : "memory");
        }
    }
}

// ---------------- logits = lstm_out @ W_out.T + b_out --------------------
__global__ void __launch_bounds__(256) logits_kernel(
    const float* __restrict__ Wout, const float* __restrict__ bout)
{
    __shared__ float Ws[7 * 512];
    int tid = threadIdx.x;
    for (int i = tid; i < 7 * 512; i += 256) Ws[i] = Wout[i];
    __syncthreads();

    int t = blockIdx.x * 8 + (tid >> 5);
    int lane = tid & 31;
    float acc[7];
#pragma unroll
    for (int j = 0; j < 7; j++) acc[j] = 0.f;
#pragma unroll
    for (int i = 0; i < 16; i++) {
        int k = lane + 32 * i;
        float v = g_lstm[(long long)t * 512 + k];
#pragma unroll
        for (int j = 0; j < 7; j++)
            acc[j] = fmaf(v, Ws[j * 512 + k], acc[j]);
    }
#pragma unroll
    for (int j = 0; j < 7; j++)
#pragma unroll
        for (int o = 16; o > 0; o >>= 1)
            acc[j] += __shfl_xor_sync(0xffffffffu, acc[j], o);
    if (lane < 7) g_logits[t * 8 + lane] = acc[lane] + bout[lane];
    else if (lane == 7) g_logits[t * 8 + 7] = 0.f;
}

// ---------------- Viterbi: replicated-fv single warp (bit-exact) ---------
__global__ void viterbi_kernel(const float* __restrict__ trans,
                               float* __restrict__ out, int out_size)
{
    __shared__ unsigned bp_s[TT];
    __shared__ __align__(16) float feat_s[2][32][8];

    int lane = threadIdx.x;
    int n = (lane < 7) ? lane : 0;
    float tn[7], tsp[7], f[7];
#pragma unroll
    for (int p = 0; p < 7; p++) tn[p] = trans[n * 7 + p];
#pragma unroll
    for (int p = 0; p < 7; p++) tsp[p] = trans[6 * 7 + p];
#pragma unroll
    for (int p = 0; p < 7; p++) f[p] = (p == 5) ? 0.f : -10000.f;

    float4 p0 = *(const float4*)&g_logits[lane * 8];
    float4 p1 = *(const float4*)&g_logits[lane * 8 + 4];
    *(float4*)&feat_s[0][lane][0] = p0;
    *(float4*)&feat_s[0][lane][4] = p1;
    __syncwarp();

    for (int tile = 0; tile < TT / 32; tile++) {
        int buf = tile & 1;
        if (tile < TT / 32 - 1) {
            const float* src = &g_logits[((tile + 1) * 32 + lane) * 8];
            p0 = *(const float4*)src;
            p1 = *(const float4*)(src + 4);
        }
        float fr[32];
#pragma unroll
        for (int i = 0; i < 32; i++) fr[i] = feat_s[buf][i][n];

        unsigned bw[4] = {0u, 0u, 0u, 0u};
#pragma unroll
        for (int s2 = 0; s2 < 32; s2++) {
            float c[7];
#pragma unroll
            for (int p = 0; p < 7; p++) c[p] = f[p] + tn[p];
            float m01 = fmaxf(c[0], c[1]), m23 = fmaxf(c[2], c[3]);
            float m45 = fmaxf(c[4], c[5]);
            float m = fmaxf(fmaxf(m01, m23), fmaxf(m45, c[6]));
            int bi = 6;
            bi = (c[5] == m) ? 5 : bi;
            bi = (c[4] == m) ? 4 : bi;
            bi = (c[3] == m) ? 3 : bi;
            bi = (c[2] == m) ? 2 : bi;
            bi = (c[1] == m) ? 1 : bi;
            bi = (c[0] == m) ? 0 : bi;
            float fnew = m + fr[s2];
#pragma unroll
            for (int p = 0; p < 7; p++) f[p] = __shfl_sync(0xffffffffu, fnew, p);
            bw[s2 >> 3] |= (unsigned)bi << (3 * (s2 & 7));
        }
#pragma unroll
        for (int s2 = 0; s2 < 32; s2++) {
            unsigned bi = (bw[s2 >> 3] >> (3 * (s2 & 7))) & 7u;
            unsigned contrib = (lane < 7) ? (bi << (3 * lane)) : 0u;
            unsigned word = __reduce_or_sync(0xffffffffu, contrib);
            if (lane == 0) bp_s[tile * 32 + s2] = word;
        }
        __syncwarp();
        if (tile < TT / 32 - 1) {
            *(float4*)&feat_s[buf ^ 1][lane][0] = p0;
            *(float4*)&feat_s[buf ^ 1][lane][4] = p1;
        }
        __syncwarp();
    }

    float tm[7];
#pragma unroll
    for (int p = 0; p < 7; p++) tm[p] = f[p] + tsp[p];
    float m01 = fmaxf(tm[0], tm[1]), m23 = fmaxf(tm[2], tm[3]);
    float m45 = fmaxf(tm[4], tm[5]);
    float bestv = fmaxf(fmaxf(m01, m23), fmaxf(m45, tm[6]));
    int bestn = 6;
    bestn = (tm[5] == bestv) ? 5 : bestn;
    bestn = (tm[4] == bestv) ? 4 : bestn;
    bestn = (tm[3] == bestv) ? 3 : bestn;
    bestn = (tm[2] == bestv) ? 2 : bestn;
    bestn = (tm[1] == bestv) ? 1 : bestn;
    bestn = (tm[0] == bestv) ? 0 : bestn;

    for (int i = 1 + TT + lane; i < out_size; i += 32) out[i] = 0.f;
    if (lane == 0) {
        out[0] = bestv;
        int tag = bestn;
        for (int t = TT - 1; t >= 0; t--) {
            out[1 + t] = (float)tag;
            tag = (int)((bp_s[t] >> (3 * tag)) & 7u);
        }
    }
}

// ---------------- launch ---------------------------------------------------
extern "C" void kernel_launch(void* const* d_in, const int* in_sizes, int n_in,
                              void* d_out, int out_size)
{
    const int*   sent  = (const int*)d_in[0];
    const float* emb   = (const float*)d_in[1];
    const float* Wihf  = (const float*)d_in[2];
    const float* Whhf  = (const float*)d_in[3];
    const float* bihf  = (const float*)d_in[4];
    const float* bhhf  = (const float*)d_in[5];
    const float* Wihb  = (const float*)d_in[6];
    const float* Whhb  = (const float*)d_in[7];
    const float* bihb  = (const float*)d_in[8];
    const float* bhhb  = (const float*)d_in[9];
    const float* h0    = (const float*)d_in[10];
    const float* c0    = (const float*)d_in[11];
    const float* Wout  = (const float*)d_in[12];
    const float* bout  = (const float*)d_in[13];
    const float* trans = (const float*)d_in[14];
    float* out = (float*)d_out;

    cudaFuncSetAttribute(lstm_kernel,
                         cudaFuncAttributeNonPortableClusterSizeAllowed, 1);

    // fork-join: xproj on a side stream, lstm concurrently on the main
    // stream gated by the g_done watermark. Streams/events created and
    // destroyed every call (no caching; all ops are capture-legal).
    cudaStream_t s2;
    cudaEvent_t e0, e1;
    cudaStreamCreateWithFlags(&s2, cudaStreamNonBlocking);
    cudaEventCreateWithFlags(&e0, cudaEventDisableTiming);
    cudaEventCreateWithFlags(&e1, cudaEventDisableTiming);

    reset_done_kernel<<<1, 256>>>();
    cudaEventRecord(e0, 0);
    cudaStreamWaitEvent(s2, e0, 0);
    xproj_kernel<<<dim3(128, 16, 2), 256, 0, s2>>>(
        sent, emb, Wihf, bihf, bhhf, Wihb, bihb, bhhb);
    cudaEventRecord(e1, s2);

    lstm_kernel<<<2 * NCL, 128>>>(Whhf, Whhb, h0, c0);

    cudaStreamWaitEvent(0, e1, 0);
    logits_kernel<<<TT / 8, 256>>>(Wout, bout);
    viterbi_kernel<<<1, 32>>>(trans, out, out_size);

    cudaEventDestroy(e0);
    cudaEventDestroy(e1);
    cudaStreamDestroy(s2);
}

// round 12
// speedup vs baseline: 1.3377x; 1.0008x over previous
#include <cuda_runtime.h>
#include <math.h>

#define TT 8192
#define NCL 16    // CTAs per direction (= cluster size) in the LSTM kernel

// ---------------- scratch (static device globals; no allocation) ----------
__device__ float g_xp[2][TT][1024];   // gate preactivations x@W_ih.T + b_ih + b_hh
__device__ float g_lstm[TT * 512];    // [T][512] = concat(hf, hb)
__device__ float g_logits[TT * 8];    // [T][8] padded (7 used)
__device__ int   g_done[2][128];      // xproj watermark: blocks finished per t-tile

__device__ __forceinline__ unsigned sm_addr(const void* p) {
    return (unsigned)__cvta_generic_to_shared(p);
}
__device__ __forceinline__ float tanh_ap(float x) {
    float y;
    asm("tanh.approx.f32 %0, %1;" : "=f"(y) : "f"(x));
    return y;
}
__device__ __forceinline__ float sig_ap(float x) {
    return fmaf(0.5f, tanh_ap(0.5f * x), 0.5f);
}

// ---------------- watermark reset (graph replays reuse counters) ----------
__global__ void reset_done_kernel() {
    if (threadIdx.x < 256) ((int*)g_done)[threadIdx.x] = 0;
}

// ---------------- x_proj GEMM: C[t][n] = emb[sent[t]] . W[n] + b1[n]+b2[n]
// dir 0 fills t-tiles ascending, dir 1 descending (consumption order).
__global__ void __launch_bounds__(256) xproj_kernel(
    const int* __restrict__ sent, const float* __restrict__ emb,
    const float* __restrict__ Wf, const float* __restrict__ b1f, const float* __restrict__ b2f,
    const float* __restrict__ Wb, const float* __restrict__ b1b, const float* __restrict__ b2b)
{
    int dir = blockIdx.z;
    const float* W  = dir ? Wb  : Wf;
    const float* b1 = dir ? b1b : b1f;
    const float* b2 = dir ? b2b : b2f;
    int ttile = dir ? (127 - (int)blockIdx.x) : (int)blockIdx.x;
    int t0 = ttile * 64;
    int n0 = blockIdx.y * 64;

    __shared__ __align__(16) float As[16][68];
    __shared__ __align__(16) float Bs[16][68];
    __shared__ int sent_s[64];

    int tid = threadIdx.x;
    if (tid < 64) sent_s[tid] = sent[t0 + tid];
    __syncthreads();

    int tx = tid & 15;
    int ty = tid >> 4;
    float acc[4][4];
#pragma unroll
    for (int i = 0; i < 4; i++)
#pragma unroll
        for (int j = 0; j < 4; j++) acc[i][j] = 0.f;

    int kk = tid & 15;
    int m0 = tid >> 4;
    for (int k0 = 0; k0 < 256; k0 += 16) {
#pragma unroll
        for (int r = 0; r < 4; r++) {
            int mm = m0 + 16 * r;
            As[kk][mm] = emb[(long long)sent_s[mm] * 256 + k0 + kk];
            Bs[kk][mm] = W[(long long)(n0 + mm) * 256 + k0 + kk];
        }
        __syncthreads();
#pragma unroll
        for (int k2 = 0; k2 < 16; k2++) {
            float4 fa = *(const float4*)&As[k2][ty * 4];
            float4 fb = *(const float4*)&Bs[k2][tx * 4];
            float a[4] = {fa.x, fa.y, fa.z, fa.w};
            float b[4] = {fb.x, fb.y, fb.z, fb.w};
#pragma unroll
            for (int i = 0; i < 4; i++)
#pragma unroll
                for (int j = 0; j < 4; j++)
                    acc[i][j] = fmaf(a[i], b[j], acc[i][j]);
        }
        __syncthreads();
    }
#pragma unroll
    for (int i = 0; i < 4; i++) {
        int t = t0 + ty * 4 + i;
#pragma unroll
        for (int j = 0; j < 4; j++) {
            int n = n0 + tx * 4 + j;
            g_xp[dir][t][n] = acc[i][j] + b1[n] + b2[n];
        }
    }
    // publish: all stores globally visible, then count this block
    __threadfence();
    __syncthreads();
    if (tid == 0) atomicAdd(&g_done[dir][ttile], 1);
}

// ---------------- BiLSTM recurrence: 16-CTA DSMEM cluster ---------------
// R9 structure + (a) all-4-gates-of-a-unit in one warp (shfl gather, act
// per-warp pre-barrier, gate_s eliminated), (b) watermark spin before each
// x prefetch tile crossing (xproj runs concurrently on a side stream).
// Arithmetic bit-identical to R9.
__global__ void __cluster_dims__(NCL, 1, 1) __launch_bounds__(128, 1) lstm_kernel(
    const float* __restrict__ Whhf, const float* __restrict__ Whhb,
    const float* __restrict__ h0, const float* __restrict__ c0)
{
    __shared__ __align__(16) float h_buf[2][16][20];
    __shared__ __align__(16) float h_stage[16];
    __shared__ __align__(16) unsigned flags[16];

    unsigned rank;
    asm("mov.u32 %0, %%cluster_ctarank;" : "=r"(rank));
    int dir  = blockIdx.x >> 4;
    int tid  = threadIdx.x;
    int w    = tid >> 5;
    int lane = tid & 31;
    int gate = lane >> 3;         // 0..3
    int ju   = (lane >> 1) & 3;   // unit within warp's 4
    int half = lane & 1;          // which 128-col half of the 256-dot
    int rowg = gate * 256 + (int)rank * 16 + w * 4 + ju;
    const float* Whh = dir ? Whhb : Whhf;

    // 32 float4 weights in registers (cols half*128 .. +127 of row rowg)
    float4 wreg[32];
    const float4* wsrc = (const float4*)(Whh + (long long)rowg * 256 + half * 128);
#pragma unroll
    for (int i = 0; i < 32; i++) wreg[i] = wsrc[i];

    // init h(0), flags, c
    for (int i = tid; i < 256; i += 128)
        h_buf[0][i >> 4][i & 15] = h0[dir * 256 + i];
    if (tid < 16) flags[tid] = 0u;
    float cst = (lane < 4) ? c0[dir * 256 + (int)rank * 16 + w * 4 + lane] : 0.f;
    __syncthreads();
    asm volatile("barrier.cluster.arrive.aligned;" ::: "memory");
    asm volatile("barrier.cluster.wait.aligned;" ::: "memory");

    unsigned flags_sa = sm_addr(flags);
    unsigned hbuf_sa  = sm_addr(h_buf);

    // pushers = warp 0 lanes 0..15: peer CTA = lane; two parity dests
    unsigned dsth0 = 0, dsth1 = 0, dstfl = 0;
    if (tid < 16) {
        unsigned l0 = hbuf_sa + (unsigned)((0 * 16 + (int)rank) * 20) * 4u;
        unsigned l1 = hbuf_sa + (unsigned)((1 * 16 + (int)rank) * 20) * 4u;
        unsigned lf = flags_sa + 4u * rank;
        asm("mapa.shared::cluster.u32 %0, %1, %2;" : "=r"(dsth0) : "r"(l0), "r"((unsigned)tid));
        asm("mapa.shared::cluster.u32 %0, %1, %2;" : "=r"(dsth1) : "r"(l1), "r"((unsigned)tid));
        asm("mapa.shared::cluster.u32 %0, %1, %2;" : "=r"(dstfl) : "r"(lf), "r"((unsigned)tid));
    }

    const float* xbase = &g_xp[dir][0][0];
    int cur_tile = -1;
    // depth-2 prefetch with watermark gating
    float xv = 0.f, xv1 = 0.f;
    if (half == 0) {
        int ta = dir ? TT - 1 : 0;
        int tb = dir ? TT - 2 : 1;
        int tla = ta >> 6;
        if (tla != cur_tile) {
            while (*(volatile int*)&g_done[dir][tla] < 16) { }
            cur_tile = tla;
        }
        xv  = __ldcg(xbase + (long long)ta * 1024 + rowg);
        int tlb = tb >> 6;
        if (tlb != cur_tile) {
            while (*(volatile int*)&g_done[dir][tlb] < 16) { }
            cur_tile = tlb;
        }
        xv1 = __ldcg(xbase + (long long)tb * 1024 + rowg);
    }

    for (int s = 1; s <= TT; s++) {
        int t = dir ? (TT - s) : (s - 1);
        int par = (s - 1) & 1;

        // prefetch x for step s+2 FIRST (watermark-gated, no flag dependency)
        float xv2 = 0.f;
        if (half == 0 && s + 2 <= TT) {
            int tn2 = dir ? (TT - s - 2) : (s + 1);
            int tl2 = tn2 >> 6;
            if (tl2 != cur_tile) {
                while (*(volatile int*)&g_done[dir][tl2] < 16) { }
                cur_tile = tl2;
            }
            xv2 = __ldcg(xbase + (long long)tn2 * 1024 + rowg);
        }

        // ---- wait until all 16 producers published h(s-1) ----
        if (s > 1) {
            unsigned need = (unsigned)(s - 1);
            while (true) {
                unsigned m = 0xffffffffu;
#pragma unroll
                for (int i = 0; i < 4; i++) {
                    unsigned f0, f1, f2, f3;
                    asm volatile("ld.volatile.shared.v4.u32 {%0,%1,%2,%3}, [%4];"
                                 : "=r"(f0), "=r"(f1), "=r"(f2), "=r"(f3)
                                 : "r"(flags_sa + 16u * i));
                    m = min(m, min(min(f0, f1), min(f2, f3)));
                }
                if (m >= need) break;
            }
#pragma unroll
            for (int i = 0; i < 16; i++) {
                unsigned tmpv;
                asm volatile("ld.acquire.cluster.shared::cta.u32 %0, [%1];"
                             : "=r"(tmpv) : "r"(flags_sa + 4u * i) : "memory");
            }
        }

        // ---- half-dot over 8 producer slices (16 floats each) ----
        float a0 = 0.f, a1 = 0.f, a2 = 0.f, a3 = 0.f;
#pragma unroll
        for (int pp = 0; pp < 8; pp++) {
            int p = half * 8 + pp;
            const float4* sp = (const float4*)&h_buf[par][p][0];
            float4 hA = sp[0]; float4 wA = wreg[pp * 4 + 0];
            a0 = fmaf(wA.x, hA.x, a0); a0 = fmaf(wA.y, hA.y, a0);
            a0 = fmaf(wA.z, hA.z, a0); a0 = fmaf(wA.w, hA.w, a0);
            float4 hB = sp[1]; float4 wB = wreg[pp * 4 + 1];
            a1 = fmaf(wB.x, hB.x, a1); a1 = fmaf(wB.y, hB.y, a1);
            a1 = fmaf(wB.z, hB.z, a1); a1 = fmaf(wB.w, hB.w, a1);
            float4 hC = sp[2]; float4 wC = wreg[pp * 4 + 2];
            a2 = fmaf(wC.x, hC.x, a2); a2 = fmaf(wC.y, hC.y, a2);
            a2 = fmaf(wC.z, hC.z, a2); a2 = fmaf(wC.w, hC.w, a2);
            float4 hD = sp[3]; float4 wD = wreg[pp * 4 + 3];
            a3 = fmaf(wD.x, hD.x, a3); a3 = fmaf(wD.y, hD.y, a3);
            a3 = fmaf(wD.z, hD.z, a3); a3 = fmaf(wD.w, hD.w, a3);
        }
        float sum = (a0 + a1) + (a2 + a3);
        sum += __shfl_xor_sync(0xffffffffu, sum, 1);   // combine the two halves
        float g = sum + xv;            // full gate preact valid on even lanes
        xv = xv1; xv1 = xv2;

        // ---- in-warp gate gather + activations (lanes 0..3 own units) ----
        int sb = 2 * (lane & 3);
        float gi = __shfl_sync(0xffffffffu, g, sb);
        float gf = __shfl_sync(0xffffffffu, g, 8 + sb);
        float gg = __shfl_sync(0xffffffffu, g, 16 + sb);
        float go = __shfl_sync(0xffffffffu, g, 24 + sb);
        if (lane < 4) {
            gi = sig_ap(gi); gf = sig_ap(gf); go = sig_ap(go);
            gg = tanh_ap(gg);
            cst = gf * cst + gi * gg;
            float hv = go * tanh_ap(cst);
            h_stage[w * 4 + lane] = hv;
            __stcg(&g_lstm[(long long)t * 512 + dir * 256 + (int)rank * 16 + w * 4 + lane], hv);
        }
        __syncthreads();   // h_stage complete; orders all h_buf(par) reads

        // ---- warp 0 lanes 0..15: push CTA's 16 h values, release flag ----
        if (tid < 16) {
            unsigned dh = (s & 1) ? dsth1 : dsth0;
            const float4* st4 = (const float4*)h_stage;
#pragma unroll
            for (int i = 0; i < 4; i++) {
                float4 v = st4[i];
                asm volatile("st.shared::cluster.v4.f32 [%0], {%1,%2,%3,%4};"
                             :: "r"(dh + 16u * i),
                                "f"(v.x), "f"(v.y), "f"(v.z), "f"(v.w) : "memory");
            }
            asm volatile("st.release.cluster.shared::cluster.u32 [%0], %1;"
                         :: "r"(dstfl), "r"((unsigned)s) : "memory");
        }
    }
}

// ---------------- logits = lstm_out @ W_out.T + b_out --------------------
__global__ void __launch_bounds__(256) logits_kernel(
    const float* __restrict__ Wout, const float* __restrict__ bout)
{
    __shared__ float Ws[7 * 512];
    int tid = threadIdx.x;
    for (int i = tid; i < 7 * 512; i += 256) Ws[i] = Wout[i];
    __syncthreads();

    int t = blockIdx.x * 8 + (tid >> 5);
    int lane = tid & 31;
    float acc[7];
#pragma unroll
    for (int j = 0; j < 7; j++) acc[j] = 0.f;
#pragma unroll
    for (int i = 0; i < 16; i++) {
        int k = lane + 32 * i;
        float v = g_lstm[(long long)t * 512 + k];
#pragma unroll
        for (int j = 0; j < 7; j++)
            acc[j] = fmaf(v, Ws[j * 512 + k], acc[j]);
    }
#pragma unroll
    for (int j = 0; j < 7; j++)
#pragma unroll
        for (int o = 16; o > 0; o >>= 1)
            acc[j] += __shfl_xor_sync(0xffffffffu, acc[j], o);
    if (lane < 7) g_logits[t * 8 + lane] = acc[lane] + bout[lane];
    else if (lane == 7) g_logits[t * 8 + 7] = 0.f;
}

// ---------------- Viterbi: replicated-fv single warp (bit-exact) ---------
__global__ void viterbi_kernel(const float* __restrict__ trans,
                               float* __restrict__ out, int out_size)
{
    __shared__ unsigned bp_s[TT];
    __shared__ __align__(16) float feat_s[2][32][8];

    int lane = threadIdx.x;
    int n = (lane < 7) ? lane : 0;
    float tn[7], tsp[7], f[7];
#pragma unroll
    for (int p = 0; p < 7; p++) tn[p] = trans[n * 7 + p];
#pragma unroll
    for (int p = 0; p < 7; p++) tsp[p] = trans[6 * 7 + p];
#pragma unroll
    for (int p = 0; p < 7; p++) f[p] = (p == 5) ? 0.f : -10000.f;

    float4 p0 = *(const float4*)&g_logits[lane * 8];
    float4 p1 = *(const float4*)&g_logits[lane * 8 + 4];
    *(float4*)&feat_s[0][lane][0] = p0;
    *(float4*)&feat_s[0][lane][4] = p1;
    __syncwarp();

    for (int tile = 0; tile < TT / 32; tile++) {
        int buf = tile & 1;
        if (tile < TT / 32 - 1) {
            const float* src = &g_logits[((tile + 1) * 32 + lane) * 8];
            p0 = *(const float4*)src;
            p1 = *(const float4*)(src + 4);
        }
        float fr[32];
#pragma unroll
        for (int i = 0; i < 32; i++) fr[i] = feat_s[buf][i][n];

        unsigned bw[4] = {0u, 0u, 0u, 0u};
#pragma unroll
        for (int s2 = 0; s2 < 32; s2++) {
            float c[7];
#pragma unroll
            for (int p = 0; p < 7; p++) c[p] = f[p] + tn[p];
            float m01 = fmaxf(c[0], c[1]), m23 = fmaxf(c[2], c[3]);
            float m45 = fmaxf(c[4], c[5]);
            float m = fmaxf(fmaxf(m01, m23), fmaxf(m45, c[6]));
            int bi = 6;
            bi = (c[5] == m) ? 5 : bi;
            bi = (c[4] == m) ? 4 : bi;
            bi = (c[3] == m) ? 3 : bi;
            bi = (c[2] == m) ? 2 : bi;
            bi = (c[1] == m) ? 1 : bi;
            bi = (c[0] == m) ? 0 : bi;
            float fnew = m + fr[s2];
#pragma unroll
            for (int p = 0; p < 7; p++) f[p] = __shfl_sync(0xffffffffu, fnew, p);
            bw[s2 >> 3] |= (unsigned)bi << (3 * (s2 & 7));
        }
#pragma unroll
        for (int s2 = 0; s2 < 32; s2++) {
            unsigned bi = (bw[s2 >> 3] >> (3 * (s2 & 7))) & 7u;
            unsigned contrib = (lane < 7) ? (bi << (3 * lane)) : 0u;
            unsigned word = __reduce_or_sync(0xffffffffu, contrib);
            if (lane == 0) bp_s[tile * 32 + s2] = word;
        }
        __syncwarp();
        if (tile < TT / 32 - 1) {
            *(float4*)&feat_s[buf ^ 1][lane][0] = p0;
            *(float4*)&feat_s[buf ^ 1][lane][4] = p1;
        }
        __syncwarp();
    }

    float tm[7];
#pragma unroll
    for (int p = 0; p < 7; p++) tm[p] = f[p] + tsp[p];
    float m01 = fmaxf(tm[0], tm[1]), m23 = fmaxf(tm[2], tm[3]);
    float m45 = fmaxf(tm[4], tm[5]);
    float bestv = fmaxf(fmaxf(m01, m23), fmaxf(m45, tm[6]));
    int bestn = 6;
    bestn = (tm[5] == bestv) ? 5 : bestn;
    bestn = (tm[4] == bestv) ? 4 : bestn;
    bestn = (tm[3] == bestv) ? 3 : bestn;
    bestn = (tm[2] == bestv) ? 2 : bestn;
    bestn = (tm[1] == bestv) ? 1 : bestn;
    bestn = (tm[0] == bestv) ? 0 : bestn;

    for (int i = 1 + TT + lane; i < out_size; i += 32) out[i] = 0.f;
    if (lane == 0) {
        out[0] = bestv;
        int tag = bestn;
        for (int t = TT - 1; t >= 0; t--) {
            out[1 + t] = (float)tag;
            tag = (int)((bp_s[t] >> (3 * tag)) & 7u);
        }
    }
}

// ---------------- launch ---------------------------------------------------
extern "C" void kernel_launch(void* const* d_in, const int* in_sizes, int n_in,
                              void* d_out, int out_size)
{
    const int*   sent  = (const int*)d_in[0];
    const float* emb   = (const float*)d_in[1];
    const float* Wihf  = (const float*)d_in[2];
    const float* Whhf  = (const float*)d_in[3];
    const float* bihf  = (const float*)d_in[4];
    const float* bhhf  = (const float*)d_in[5];
    const float* Wihb  = (const float*)d_in[6];
    const float* Whhb  = (const float*)d_in[7];
    const float* bihb  = (const float*)d_in[8];
    const float* bhhb  = (const float*)d_in[9];
    const float* h0    = (const float*)d_in[10];
    const float* c0    = (const float*)d_in[11];
    const float* Wout  = (const float*)d_in[12];
    const float* bout  = (const float*)d_in[13];
    const float* trans = (const float*)d_in[14];
    float* out = (float*)d_out;

    cudaFuncSetAttribute(lstm_kernel,
                         cudaFuncAttributeNonPortableClusterSizeAllowed, 1);

    // fork-join: xproj on a side stream, lstm concurrently on the main
    // stream gated by the g_done watermark. Streams/events created and
    // destroyed every call (no caching; all ops are capture-legal).
    cudaStream_t s2;
    cudaEvent_t e0, e1;
    cudaStreamCreateWithFlags(&s2, cudaStreamNonBlocking);
    cudaEventCreateWithFlags(&e0, cudaEventDisableTiming);
    cudaEventCreateWithFlags(&e1, cudaEventDisableTiming);

    reset_done_kernel<<<1, 256>>>();
    cudaEventRecord(e0, 0);
    cudaStreamWaitEvent(s2, e0, 0);
    xproj_kernel<<<dim3(128, 16, 2), 256, 0, s2>>>(
        sent, emb, Wihf, bihf, bhhf, Wihb, bihb, bhhb);
    cudaEventRecord(e1, s2);

    lstm_kernel<<<2 * NCL, 128>>>(Whhf, Whhb, h0, c0);

    cudaStreamWaitEvent(0, e1, 0);
    logits_kernel<<<TT / 8, 256>>>(Wout, bout);
    viterbi_kernel<<<1, 32>>>(trans, out, out_size);

    cudaEventDestroy(e0);
    cudaEventDestroy(e1);
    cudaStreamDestroy(s2);
}